// round 7
// baseline (speedup 1.0000x reference)
#include <cuda_runtime.h>
#include <cstddef>
#include <cstdint>

#define NEGV -1000000000.0f
#define HDIM 128
#define NMAX 12288
#define EMAX 393216

__device__ float2   g_p[NMAX];
__device__ float    g_vals[EMAX];
__device__ uint32_t g_addr[EMAX];
__device__ int      g_done;

__global__ void reset_kernel() { g_done = 0; }

#define N_PART_BLKS 384
#define N_VALS_BLKS 192

__global__ void __launch_bounds__(256)
fused_kernel(const float* __restrict__ h,
             const int* __restrict__ sources,
             const int* __restrict__ dests,
             const float* __restrict__ weights,
             const float* __restrict__ W,
             const float* __restrict__ b,
             float4* __restrict__ out,
             int N, int E, int n4) {
    const int tid = threadIdx.x;
    const int bid = blockIdx.x;

    if (bid < N_PART_BLKS) {
        // ---- partials: 8 lanes/node, 4 nodes/warp, 32 nodes/block
        const int warp = tid >> 5;
        const int lane = tid & 31;
        const int sub  = lane & 7;
        const int grp  = lane >> 3;
        const int node = bid * 32 + warp * 4 + grp;
        if (node < N) {
            const float* hp = h + (size_t)node * HDIM + sub * 16;
            const float* wp = W + sub * 16;
            float ad = 0.0f, as = 0.0f;
            #pragma unroll
            for (int k = 0; k < 4; k++) {
                const float4 hv = *reinterpret_cast<const float4*>(hp + k * 4);
                const float4 wd = *reinterpret_cast<const float4*>(wp + k * 4);
                const float4 ws = *reinterpret_cast<const float4*>(wp + HDIM + k * 4);
                ad += hv.x * wd.x + hv.y * wd.y + hv.z * wd.z + hv.w * wd.w;
                as += hv.x * ws.x + hv.y * ws.y + hv.z * ws.z + hv.w * ws.w;
            }
            #pragma unroll
            for (int o = 4; o; o >>= 1) {
                ad += __shfl_xor_sync(0xffffffffu, ad, o);
                as += __shfl_xor_sync(0xffffffffu, as, o);
            }
            if (sub == 0) g_p[node] = make_float2(ad, as);
        }
        __syncthreads();
        if (tid == 0) {
            __threadfence();
            atomicAdd(&g_done, 1);
        }
    } else if (bid < N_PART_BLKS + N_VALS_BLKS) {
        // ---- vals: wait ONLY for partials (384 arrivals), never for fill.
        if (tid == 0) {
            while (atomicAdd(&g_done, 0) < N_PART_BLKS) __nanosleep(64);
        }
        __syncthreads();
        __threadfence();

        const int vbid = bid - N_PART_BLKS;
        const float wW = __ldg(W + 2 * HDIM);
        const float bb = __ldg(b);
        const int stride = N_VALS_BLKS * 256;
        for (int e = vbid * 256 + tid; e < E; e += stride) {
            const int s = sources[e];
            const int d = dests[e];
            const float2 pd = __ldg(&g_p[d]);
            const float2 ps = __ldg(&g_p[s]);
            g_vals[e] = pd.x + ps.y + weights[e] * wW + bb;
            g_addr[e] = (uint32_t)d * (uint32_t)N + (uint32_t)s;
        }
    } else {
        // ---- fill: plain float4 stores, no fences, the 6.98 TB/s path
        const int fbid = bid - (N_PART_BLKS + N_VALS_BLKS);
        const float4 v = make_float4(NEGV, NEGV, NEGV, NEGV);
        const int base = fbid * 1024 + tid;
        #pragma unroll
        for (int k = 0; k < 4; k++) {
            int idx = base + k * 256;
            if (idx < n4) out[idx] = v;
        }
    }
}

// Pure scatter epilogue: two contiguous 4B loads + one scattered 4B store.
__global__ void __launch_bounds__(256)
epilogue_kernel(float* __restrict__ out, int E) {
    int e = blockIdx.x * blockDim.x + threadIdx.x;
    if (e < E) {
        out[g_addr[e]] = g_vals[e];
    }
}

extern "C" void kernel_launch(void* const* d_in, const int* in_sizes, int n_in,
                              void* d_out, int out_size) {
    const float* h       = (const float*)d_in[0];
    const int*   sources = (const int*)d_in[1];
    const int*   dests   = (const int*)d_in[2];
    const float* weights = (const float*)d_in[3];
    const float* W       = (const float*)d_in[4];
    const float* b       = (const float*)d_in[5];
    float* out = (float*)d_out;

    const int N = in_sizes[0] / HDIM;     // 12288
    const int E = in_sizes[1];            // 393216

    long long total = (long long)N * N;
    int n4 = (int)(total >> 2);           // 37,748,736

    const int nFillBlks = (n4 + 1023) / 1024;       // 36,864

    reset_kernel<<<1, 1>>>();
    fused_kernel<<<N_PART_BLKS + N_VALS_BLKS + nFillBlks, 256>>>(
        h, sources, dests, weights, W, b, (float4*)out, N, E, n4);
    epilogue_kernel<<<(E + 255) / 256, 256>>>(out, E);
}